// round 8
// baseline (speedup 1.0000x reference)
#include <cuda_runtime.h>
#include <cuda_bf16.h>
#include <cstdint>

// Problem constants (fixed shapes per reference)
#define CC 9
#define HH 180
#define WW 240
#define BB 8
#define NN 100000
#define TOTAL_EVENTS (BB * NN)          // 800000
#define HW (HH * WW)                    // 43200
#define CHW (CC * HW)                   // 388800
#define VOX_PER_BATCH (2 * CHW)         // 777600
#define NUM_VOX (BB * VOX_PER_BATCH)    // 6220800

// Scratch accumulator: layout (b, p, y, x, bin), bin padded 9 -> 12 floats
// (48B/cell, 16B aligned): the 9 bins of one event are 2x red.v4 + 1x red.f32.
// INVARIANT: this buffer is zero at entry to every kernel_launch call.
// __device__ globals are zero-initialized at module load, and the transpose
// kernel re-zeroes every cell after consuming it, so each launch (correctness
// run, capture, every replay) sees zeros and leaves zeros. No zero-fill pass.
#define NCELLS (BB * 2 * HW)            // 691200
#define CELL_F 12
__device__ float4 g_vox_alt4[NCELLS * CELL_F / 4];   // 33.2 MB, 16B-aligned

// LUT over ts in [-1, 1]. LUT_N-1 = 2048 -> h = 1/1024; bin offset 1/8 = 128*h (exact)
#define LUT_N 2049
#define LUT_SCALE 1024.0f
#define LUT_BIN_STEP 128

#define SAMPLES_PER_BLOCK 16            // 256 threads / 16 lanes per sample
#define LUT_BLOCKS ((LUT_N + SAMPLES_PER_BLOCK - 1) / SAMPLES_PER_BLOCK)  // 129

#define KPAD 112                        // hidden dim padded to 112 (4 quarters of 28)

__device__ float g_lut[LUT_N];

// ---------------------------------------------------------------------------
// LUT kernel: 16 lanes per sample. Lane (q_j, q_k) owns layer-1 units
// j in [25*q_j,+25) and layer-2 outputs k in [28*q_k,+28). w2 staged into
// padded smem via 2500 linear float4 loads (w2 rows are 25 float4s, so the
// flat float4 index is r*25+m -> ~10 pipelined LDG.128 per thread, no
// divides on the hot path). Partials combine with shfl_xor.
// ---------------------------------------------------------------------------
__global__ __launch_bounds__(256)
void lut_kernel(const float* __restrict__ w1, const float* __restrict__ b1,
                const float* __restrict__ w2, const float* __restrict__ b2,
                const float* __restrict__ w3, const float* __restrict__ b3)
{
    __shared__ float s_w2[100 * KPAD];    // 44.8 KB, zero-padded columns
    __shared__ float s_b2[KPAD];
    __shared__ float s_w3[KPAD];

    // Stage w2: 2500 float4s, linear in gmem, padded rows in smem.
    const float4* w2v = reinterpret_cast<const float4*>(w2);
    for (int i4 = threadIdx.x; i4 < 2500; i4 += 256) {
        int r = i4 / 25;                 // constant divide -> mulhi
        int m = i4 - r * 25;
        float4 w = __ldg(w2v + i4);
        *reinterpret_cast<float4*>(s_w2 + r * KPAD + m * 4) = w;
    }
    // Zero the pad columns 100..111 of each row.
    for (int i = threadIdx.x; i < 100 * 12; i += 256) {
        int r = i / 12;
        s_w2[r * KPAD + 100 + (i - r * 12)] = 0.0f;
    }
    if (threadIdx.x < KPAD) {
        s_b2[threadIdx.x] = (threadIdx.x < 100) ? b2[threadIdx.x] : 0.0f;
        s_w3[threadIdx.x] = (threadIdx.x < 100) ? w3[threadIdx.x] : 0.0f;
    }
    __syncthreads();

    int t = blockIdx.x * 256 + threadIdx.x;
    int s = t >> 4;
    if (s >= LUT_N) return;
    int q_j = t & 3;
    int q_k = (t >> 2) & 3;

    float ts = -1.0f + (float)s * (1.0f / 1024.0f);

    // Layer 1: my 25 units
    float h[25];
    int jbase = q_j * 25;
    #pragma unroll
    for (int jj = 0; jj < 25; jj++) {
        float hv = fmaf(ts, __ldg(w1 + jbase + jj), __ldg(b1 + jbase + jj));
        h[jj] = (hv > 0.0f) ? hv : 0.1f * hv;
    }

    // Layer 2 partial: my 28 k's over my 25 j's
    int kbase = q_k * 28;
    float acc[28];
    #pragma unroll
    for (int kk = 0; kk < 28; kk++)
        acc[kk] = (q_j == 0) ? s_b2[kbase + kk] : 0.0f;

    #pragma unroll
    for (int jj = 0; jj < 25; jj++) {
        float hv = h[jj];
        const float4* row = reinterpret_cast<const float4*>(s_w2 + (jbase + jj) * KPAD + kbase);
        #pragma unroll
        for (int m = 0; m < 7; m++) {
            float4 w = row[m];
            acc[m * 4 + 0] = fmaf(hv, w.x, acc[m * 4 + 0]);
            acc[m * 4 + 1] = fmaf(hv, w.y, acc[m * 4 + 1]);
            acc[m * 4 + 2] = fmaf(hv, w.z, acc[m * 4 + 2]);
            acc[m * 4 + 3] = fmaf(hv, w.w, acc[m * 4 + 3]);
        }
    }

    // Combine j-quarters (bits0-1 of lane = q_j)
    #pragma unroll
    for (int kk = 0; kk < 28; kk++) {
        acc[kk] += __shfl_xor_sync(0xffffffffu, acc[kk], 1);
        acc[kk] += __shfl_xor_sync(0xffffffffu, acc[kk], 2);
    }

    // Layer 3 partial (pads: acc==0 -> leaky==0, s_w3 pad==0)
    float part = 0.0f;
    #pragma unroll
    for (int kk = 0; kk < 28; kk++) {
        float a = acc[kk];
        a = (a > 0.0f) ? a : 0.1f * a;
        part = fmaf(a, s_w3[kbase + kk], part);
    }
    part += __shfl_xor_sync(0xffffffffu, part, 4);
    part += __shfl_xor_sync(0xffffffffu, part, 8);

    if ((t & 15) == 0) g_lut[s] = part + __ldg(b3);
}

// ---------------------------------------------------------------------------
// Scatter: accumulate into (b,p,y,x,bin) scratch. The 9 bin-values of one
// event live in one 48B cell -> 2x red.global.add.v4.f32 + 1x red scalar
// (3 L2 sectors per event instead of 9 strided lines). LUT as overlapping
// float2 pairs in 16KB smem; all 9 bins share the interpolation fraction.
// ---------------------------------------------------------------------------
__device__ __forceinline__ void scatter_one(float tv, int xx, int yy, int pp,
                                            int bp2, const float2* slut2)
{
    int cell = (bp2 + pp) * HW + yy * WW + xx;
    float* cp = reinterpret_cast<float*>(g_vox_alt4) + cell * CELL_F;

    float u = fmaf(tv, LUT_SCALE, LUT_SCALE);     // in [1024, 2048)
    int   j0 = (int)u;
    float f  = u - (float)j0;

    float v[9];
    #pragma unroll
    for (int i = 0; i < CC; i++) {
        float2 vv = slut2[j0 - LUT_BIN_STEP * i]; // index in [0, 2047]
        v[i] = tv * fmaf(f, vv.y - vv.x, vv.x);
    }

    asm volatile("red.global.add.v4.f32 [%0], {%1, %2, %3, %4};"
                 :: "l"(cp), "f"(v[0]), "f"(v[1]), "f"(v[2]), "f"(v[3]) : "memory");
    asm volatile("red.global.add.v4.f32 [%0], {%1, %2, %3, %4};"
                 :: "l"(cp + 4), "f"(v[4]), "f"(v[5]), "f"(v[6]), "f"(v[7]) : "memory");
    asm volatile("red.global.add.f32 [%0], %1;"
                 :: "l"(cp + 8), "f"(v[8]) : "memory");
}

__global__ __launch_bounds__(256)
void scatter_kernel(const float* __restrict__ t,
                    const int* __restrict__ x,
                    const int* __restrict__ y,
                    const int* __restrict__ p)
{
    __shared__ float2 slut2[LUT_N - 1];           // 2048 pairs, 16 KB
    for (int i = threadIdx.x; i < LUT_N - 1; i += 256)
        slut2[i] = make_float2(g_lut[i], g_lut[i + 1]);
    __syncthreads();

    int v = blockIdx.x * 256 + threadIdx.x;       // vec4 event index
    if (v >= TOTAL_EVENTS / 4) return;

    float4 t4 = __ldg(reinterpret_cast<const float4*>(t) + v);
    int4   x4 = __ldg(reinterpret_cast<const int4*>(x) + v);
    int4   y4 = __ldg(reinterpret_cast<const int4*>(y) + v);
    int4   p4 = __ldg(reinterpret_cast<const int4*>(p) + v);

    // NN/4 = 25000: all 4 events of a vec4 share the same batch
    int bp2 = (v / (NN / 4)) * 2;                 // b*2

    scatter_one(t4.x, x4.x, y4.x, p4.x, bp2, slut2);
    scatter_one(t4.y, x4.y, y4.y, p4.y, bp2, slut2);
    scatter_one(t4.z, x4.z, y4.z, p4.z, bp2, slut2);
    scatter_one(t4.w, x4.w, y4.w, p4.w, bp2, slut2);
}

// ---------------------------------------------------------------------------
// Transpose + consume: (b,p,y,x,bin) scratch -> (b, p*C+bin, y, x) output,
// then RE-ZERO the scratch cell (restores the zero-at-entry invariant for
// the next launch; the zero writes hit L2-resident lines). 3 LDG.128 +
// 3 STG.128(zero) + 9 coalesced STG.32 per cell. Overwrites every output
// element -> d_out needs no zeroing either.
// ---------------------------------------------------------------------------
__global__ __launch_bounds__(256)
void transpose_kernel(float* __restrict__ out)
{
    int c = blockIdx.x * 256 + threadIdx.x;       // cell = (b*2+p)*HW + y*W + x
    if (c >= NCELLS) return;

    int bp = c / HW;
    int yx = c - bp * HW;
    // out index for bin i: b*2CHW + p*CHW + i*HW + yx == bp*CHW + i*HW + yx
    int obase = bp * CHW + yx;

    float4* src = g_vox_alt4 + c * 3;
    float4 a0 = src[0];
    float4 a1 = src[1];
    float4 a2 = src[2];

    float4 z = make_float4(0.f, 0.f, 0.f, 0.f);
    src[0] = z;
    src[1] = z;
    src[2] = z;

    out[obase + 0 * HW] = a0.x;
    out[obase + 1 * HW] = a0.y;
    out[obase + 2 * HW] = a0.z;
    out[obase + 3 * HW] = a0.w;
    out[obase + 4 * HW] = a1.x;
    out[obase + 5 * HW] = a1.y;
    out[obase + 6 * HW] = a1.z;
    out[obase + 7 * HW] = a1.w;
    out[obase + 8 * HW] = a2.x;
}

// ---------------------------------------------------------------------------
// Launch: LUT -> scatter -> transpose(+re-zero). Graph-capturable,
// allocation-free. No zero-fill pass anywhere.
// ---------------------------------------------------------------------------
extern "C" void kernel_launch(void* const* d_in, const int* in_sizes, int n_in,
                              void* d_out, int out_size)
{
    const float* t  = (const float*)d_in[0];
    const float* w1 = (const float*)d_in[1];
    const float* b1 = (const float*)d_in[2];
    const float* w2 = (const float*)d_in[3];
    const float* b2 = (const float*)d_in[4];
    const float* w3 = (const float*)d_in[5];
    const float* b3 = (const float*)d_in[6];
    const int*   x  = (const int*)d_in[7];
    const int*   y  = (const int*)d_in[8];
    const int*   p  = (const int*)d_in[9];
    float* out = (float*)d_out;

    lut_kernel<<<LUT_BLOCKS, 256>>>(w1, b1, w2, b2, w3, b3);

    const int nvec = TOTAL_EVENTS / 4;            // 200000
    scatter_kernel<<<(nvec + 255) / 256, 256>>>(t, x, y, p);

    transpose_kernel<<<(NCELLS + 255) / 256, 256>>>(out);
}

// round 9
// speedup vs baseline: 1.0597x; 1.0597x over previous
#include <cuda_runtime.h>
#include <cuda_bf16.h>
#include <cstdint>

// Problem constants (fixed shapes per reference)
#define CC 9
#define HH 180
#define WW 240
#define BB 8
#define NN 100000
#define TOTAL_EVENTS (BB * NN)          // 800000
#define HW (HH * WW)                    // 43200
#define CHW (CC * HW)                   // 388800
#define VOX_PER_BATCH (2 * CHW)         // 777600
#define NUM_VOX (BB * VOX_PER_BATCH)    // 6220800

// Scratch accumulator: layout (b, p, y, x, bin), bin padded 9 -> 12 floats
// (48B/cell): the 9 bins of one event are 2x red.v4 + 1x red.f32.
// Zero-filled by prep each launch (the zero pass doubles as an L2 warm for
// the scatter atomics — removing it regressed scatter in R8).
#define NCELLS (BB * 2 * HW)            // 691200
#define CELL_F 12
__device__ float4 g_vox_alt4[NCELLS * CELL_F / 4];   // 33.2 MB, 16B-aligned

// LUT over ts in [-1, 1]. LUT_N-1 = 2048 -> h = 1/1024; bin offset 1/8 = 128*h (exact)
#define LUT_N 2049
#define LUT_SCALE 1024.0f
#define LUT_BIN_STEP 128

#define ZBLOCKS 148                     // zero-fill blocks (one wave, BW-bound)
#define SAMPLES_PER_BLOCK 8             // 256 threads / 32 lanes per sample
#define LUT_BLOCKS ((LUT_N + SAMPLES_PER_BLOCK - 1) / SAMPLES_PER_BLOCK)  // 257

#define KPAD 128                        // hidden dim padded to 128 (8 slices of 16)

__device__ float g_lut[LUT_N];

// ---------------------------------------------------------------------------
// Prep kernel (heterogeneous blocks, all co-resident):
//   blocks [0, ZBLOCKS): zero the 33.2MB scratch (DRAM-BW bound ~4us; also
//   warms L2 for the scatter atomics).
//   blocks [ZBLOCKS, +LUT_BLOCKS): build the LUT, 32 lanes per sample.
// Lane (q_j, q_k): q_j in [0,4) owns layer-1 units j in [25*q_j,+25);
// q_k in [0,8) owns layer-2 outputs k in [16*q_k,+16) (zero-padded to 128).
// w2 staged zero-padded into 51.2KB smem (divide-free indexing); inner loop
// is broadcast LDS.128. Partials combine via shfl_xor: (1,2) over q_j, then
// layer-3 partial dot, then (4,8,16) over q_k. 257 blocks -> ~2.7/SM
// co-resident so staging latency of one block hides behind another's compute.
// ---------------------------------------------------------------------------
__global__ __launch_bounds__(256)
void prep_kernel(const float* __restrict__ w1, const float* __restrict__ b1,
                 const float* __restrict__ w2, const float* __restrict__ b2,
                 const float* __restrict__ w3, const float* __restrict__ b3)
{
    if (blockIdx.x < ZBLOCKS) {
        const int total4 = NCELLS * CELL_F / 4;       // 2,073,600 float4s
        float4 z = make_float4(0.f, 0.f, 0.f, 0.f);
        int tid = blockIdx.x * 256 + threadIdx.x;
        for (int i = tid; i < total4; i += ZBLOCKS * 256)
            g_vox_alt4[i] = z;
        return;
    }

    // ---- LUT build path ----
    __shared__ float s_w2[100 * KPAD];    // 51.2 KB, zero-padded columns
    __shared__ float s_b2[KPAD];
    __shared__ float s_w3[KPAD];

    // Stage w2: smem rows are 32 float4s -> r = i4>>5, m = i4&31 (no divide).
    const float4* w2v = reinterpret_cast<const float4*>(w2);
    for (int i4 = threadIdx.x; i4 < 100 * 32; i4 += 256) {
        int r = i4 >> 5;
        int m = i4 & 31;
        float4 w = (m < 25) ? __ldg(w2v + r * 25 + m)
                            : make_float4(0.f, 0.f, 0.f, 0.f);
        *reinterpret_cast<float4*>(s_w2 + r * KPAD + m * 4) = w;
    }
    if (threadIdx.x < KPAD) {
        s_b2[threadIdx.x] = (threadIdx.x < 100) ? b2[threadIdx.x] : 0.0f;
        s_w3[threadIdx.x] = (threadIdx.x < 100) ? w3[threadIdx.x] : 0.0f;
    }
    __syncthreads();

    int t = (blockIdx.x - ZBLOCKS) * 256 + threadIdx.x;
    int s = t >> 5;                      // sample index (one warp per sample)
    if (s >= LUT_N) return;
    int q_j = t & 3;
    int q_k = (t >> 2) & 7;

    float ts = -1.0f + (float)s * (1.0f / 1024.0f);

    // Layer 1: my 25 units
    float h[25];
    int jbase = q_j * 25;
    #pragma unroll
    for (int jj = 0; jj < 25; jj++) {
        float hv = fmaf(ts, __ldg(w1 + jbase + jj), __ldg(b1 + jbase + jj));
        h[jj] = (hv > 0.0f) ? hv : 0.1f * hv;
    }

    // Layer 2 partial: my 16 k's over my 25 j's
    int kbase = q_k * 16;
    float acc[16];
    #pragma unroll
    for (int kk = 0; kk < 16; kk++)
        acc[kk] = (q_j == 0) ? s_b2[kbase + kk] : 0.0f;

    #pragma unroll
    for (int jj = 0; jj < 25; jj++) {
        float hv = h[jj];
        const float4* row = reinterpret_cast<const float4*>(s_w2 + (jbase + jj) * KPAD + kbase);
        #pragma unroll
        for (int m = 0; m < 4; m++) {
            float4 w = row[m];
            acc[m * 4 + 0] = fmaf(hv, w.x, acc[m * 4 + 0]);
            acc[m * 4 + 1] = fmaf(hv, w.y, acc[m * 4 + 1]);
            acc[m * 4 + 2] = fmaf(hv, w.z, acc[m * 4 + 2]);
            acc[m * 4 + 3] = fmaf(hv, w.w, acc[m * 4 + 3]);
        }
    }

    // Combine j-quarters (bits 0-1 of lane = q_j)
    #pragma unroll
    for (int kk = 0; kk < 16; kk++) {
        acc[kk] += __shfl_xor_sync(0xffffffffu, acc[kk], 1);
        acc[kk] += __shfl_xor_sync(0xffffffffu, acc[kk], 2);
    }

    // Layer 3 partial (pads: acc==0 -> leaky==0, s_w3 pad==0)
    float part = 0.0f;
    #pragma unroll
    for (int kk = 0; kk < 16; kk++) {
        float a = acc[kk];
        a = (a > 0.0f) ? a : 0.1f * a;
        part = fmaf(a, s_w3[kbase + kk], part);
    }
    // Combine k-slices (bits 2-4 of lane = q_k)
    part += __shfl_xor_sync(0xffffffffu, part, 4);
    part += __shfl_xor_sync(0xffffffffu, part, 8);
    part += __shfl_xor_sync(0xffffffffu, part, 16);

    if ((t & 31) == 0) g_lut[s] = part + __ldg(b3);
}

// ---------------------------------------------------------------------------
// Scatter: accumulate into (b,p,y,x,bin) scratch. The 9 bin-values of one
// event live in one 48B cell -> 2x red.global.add.v4.f32 + 1x red scalar
// (3 L2 sectors per event instead of 9 strided lines). LUT as overlapping
// float2 pairs in 16KB smem; all 9 bins share the interpolation fraction.
// ---------------------------------------------------------------------------
__device__ __forceinline__ void scatter_one(float tv, int xx, int yy, int pp,
                                            int bp2, const float2* slut2)
{
    int cell = (bp2 + pp) * HW + yy * WW + xx;
    float* cp = reinterpret_cast<float*>(g_vox_alt4) + cell * CELL_F;

    float u = fmaf(tv, LUT_SCALE, LUT_SCALE);     // in [1024, 2048)
    int   j0 = (int)u;
    float f  = u - (float)j0;

    float v[9];
    #pragma unroll
    for (int i = 0; i < CC; i++) {
        float2 vv = slut2[j0 - LUT_BIN_STEP * i]; // index in [0, 2047]
        v[i] = tv * fmaf(f, vv.y - vv.x, vv.x);
    }

    asm volatile("red.global.add.v4.f32 [%0], {%1, %2, %3, %4};"
                 :: "l"(cp), "f"(v[0]), "f"(v[1]), "f"(v[2]), "f"(v[3]) : "memory");
    asm volatile("red.global.add.v4.f32 [%0], {%1, %2, %3, %4};"
                 :: "l"(cp + 4), "f"(v[4]), "f"(v[5]), "f"(v[6]), "f"(v[7]) : "memory");
    asm volatile("red.global.add.f32 [%0], %1;"
                 :: "l"(cp + 8), "f"(v[8]) : "memory");
}

__global__ __launch_bounds__(256)
void scatter_kernel(const float* __restrict__ t,
                    const int* __restrict__ x,
                    const int* __restrict__ y,
                    const int* __restrict__ p)
{
    __shared__ float2 slut2[LUT_N - 1];           // 2048 pairs, 16 KB
    for (int i = threadIdx.x; i < LUT_N - 1; i += 256)
        slut2[i] = make_float2(g_lut[i], g_lut[i + 1]);
    __syncthreads();

    int v = blockIdx.x * 256 + threadIdx.x;       // vec4 event index
    if (v >= TOTAL_EVENTS / 4) return;

    float4 t4 = __ldg(reinterpret_cast<const float4*>(t) + v);
    int4   x4 = __ldg(reinterpret_cast<const int4*>(x) + v);
    int4   y4 = __ldg(reinterpret_cast<const int4*>(y) + v);
    int4   p4 = __ldg(reinterpret_cast<const int4*>(p) + v);

    // NN/4 = 25000: all 4 events of a vec4 share the same batch
    int bp2 = (v / (NN / 4)) * 2;                 // b*2

    scatter_one(t4.x, x4.x, y4.x, p4.x, bp2, slut2);
    scatter_one(t4.y, x4.y, y4.y, p4.y, bp2, slut2);
    scatter_one(t4.z, x4.z, y4.z, p4.z, bp2, slut2);
    scatter_one(t4.w, x4.w, y4.w, p4.w, bp2, slut2);
}

// ---------------------------------------------------------------------------
// Transpose: (b,p,y,x,bin) scratch -> (b, p*C+bin, y, x) output. One thread
// per cell: 3 LDG.128 (contiguous, L2-resident) + 9 coalesced STG.32.
// Overwrites every output element -> d_out needs no zeroing.
// ---------------------------------------------------------------------------
__global__ __launch_bounds__(256)
void transpose_kernel(float* __restrict__ out)
{
    int c = blockIdx.x * 256 + threadIdx.x;       // cell = (b*2+p)*HW + y*W + x
    if (c >= NCELLS) return;

    int bp = c / HW;
    int yx = c - bp * HW;
    int obase = bp * CHW + yx;                    // bin i -> obase + i*HW

    const float4* src = g_vox_alt4 + c * 3;
    float4 a0 = src[0];
    float4 a1 = src[1];
    float4 a2 = src[2];

    out[obase + 0 * HW] = a0.x;
    out[obase + 1 * HW] = a0.y;
    out[obase + 2 * HW] = a0.z;
    out[obase + 3 * HW] = a0.w;
    out[obase + 4 * HW] = a1.x;
    out[obase + 5 * HW] = a1.y;
    out[obase + 6 * HW] = a1.z;
    out[obase + 7 * HW] = a1.w;
    out[obase + 8 * HW] = a2.x;
}

// ---------------------------------------------------------------------------
// Launch: prep (zero scratch + LUT, one heterogeneous kernel) -> scatter ->
// transpose. Graph-capturable, allocation-free.
// ---------------------------------------------------------------------------
extern "C" void kernel_launch(void* const* d_in, const int* in_sizes, int n_in,
                              void* d_out, int out_size)
{
    const float* t  = (const float*)d_in[0];
    const float* w1 = (const float*)d_in[1];
    const float* b1 = (const float*)d_in[2];
    const float* w2 = (const float*)d_in[3];
    const float* b2 = (const float*)d_in[4];
    const float* w3 = (const float*)d_in[5];
    const float* b3 = (const float*)d_in[6];
    const int*   x  = (const int*)d_in[7];
    const int*   y  = (const int*)d_in[8];
    const int*   p  = (const int*)d_in[9];
    float* out = (float*)d_out;

    prep_kernel<<<ZBLOCKS + LUT_BLOCKS, 256>>>(w1, b1, w2, b2, w3, b3);

    const int nvec = TOTAL_EVENTS / 4;            // 200000
    scatter_kernel<<<(nvec + 255) / 256, 256>>>(t, x, y, p);

    transpose_kernel<<<(NCELLS + 255) / 256, 256>>>(out);
}